// round 5
// baseline (speedup 1.0000x reference)
#include <cuda_runtime.h>
#include <cstdint>

#define Nn     8192
#define IND    128
#define HID    32
#define BM     128
#define BKB    64                 // k bytes (= elements, u8) per tile
#define KSPLIT 8
#define KCHUNK (Nn / KSPLIT)      // 1024
#define NTILE  (KCHUNK / BKB)     // 16
#define APITCH 80                 // padded row pitch (bytes), conflict-free
#define ASZ    (BM * APITCH)      // 10240
#define BSZ    (HID * APITCH)     // 2560
#define STAGE  (ASZ + BSZ)        // 12800
#define NSTAGE 3

// Scratch (static device arrays only; no allocations)
__device__ unsigned char g_adjq[(size_t)Nn * Nn];     // u8 adj (64 MB)
__device__ float         g_dinv[Nn];
__device__ float         g_zs[Nn * HID];              // fp32 zs (exact self-loop term)
__device__ signed char   g_zqT[(size_t)HID * Nn];     // s8 zs transposed [c][j]
__device__ float         g_h[Nn * HID];
__device__ int           g_part[(size_t)KSPLIT * Nn * HID];  // s32 partials
__device__ unsigned      g_cmbits[2][HID];            // per-column absmax (as uint bits)

// ---------------------------------------------------------------------------
__device__ __forceinline__ uint32_t smem_u32(const void* p) {
    uint32_t a;
    asm("{ .reg .u64 t; cvta.to.shared.u64 t, %1; cvt.u32.u64 %0, t; }" : "=r"(a) : "l"(p));
    return a;
}
__device__ __forceinline__ void cp16(uint32_t dst, const void* src) {
    asm volatile("cp.async.ca.shared.global [%0], [%1], 16;" :: "r"(dst), "l"(src));
}

// ---------------------------------------------------------------------------
// 1) degree + u8 convert: dinv = rsqrt(max(1,1+rowsum)); adjq = round(adj*255)
//    block 0 also clears the colmax accumulators for both layers.
// ---------------------------------------------------------------------------
__global__ __launch_bounds__(256) void degree_convert_kernel(const float* __restrict__ adj) {
    if (blockIdx.x == 0 && threadIdx.x < 2 * HID)
        reinterpret_cast<unsigned*>(g_cmbits)[threadIdx.x] = 0u;
    int row = blockIdx.x;
    const float4* rp = reinterpret_cast<const float4*>(adj + (size_t)row * Nn);
    uchar4* qp = reinterpret_cast<uchar4*>(g_adjq + (size_t)row * Nn);
    float s = 0.f;
    for (int i = threadIdx.x; i < Nn / 4; i += 256) {
        float4 v = rp[i];
        s += (v.x + v.y) + (v.z + v.w);
        uchar4 q;
        q.x = (unsigned char)__float2int_rn(v.x * 255.f);
        q.y = (unsigned char)__float2int_rn(v.y * 255.f);
        q.z = (unsigned char)__float2int_rn(v.z * 255.f);
        q.w = (unsigned char)__float2int_rn(v.w * 255.f);
        qp[i] = q;
    }
#pragma unroll
    for (int o = 16; o; o >>= 1) s += __shfl_down_sync(0xffffffffu, s, o);
    __shared__ float ws[8];
    int lane = threadIdx.x & 31, w = threadIdx.x >> 5;
    if (lane == 0) ws[w] = s;
    __syncthreads();
    if (threadIdx.x == 0) {
        float d = 1.0f;  // self loop
#pragma unroll
        for (int i = 0; i < 8; i++) d += ws[i];
        d = fmaxf(d, 1.0f);
        g_dinv[row] = rsqrtf(d);
    }
}

// ---------------------------------------------------------------------------
// column-absmax block reduce + atomicMax (shared by z1/z2)
// ---------------------------------------------------------------------------
__device__ __forceinline__ void colmax_update(float v, int tid, int c, int layer) {
    __shared__ float red[256];
    red[tid] = fabsf(v);
    __syncthreads();
    if (tid < 128) red[tid] = fmaxf(red[tid], red[tid + 128]);
    __syncthreads();
    if (tid < 64) red[tid] = fmaxf(red[tid], red[tid + 64]);
    __syncthreads();
    if (tid < 32) {
        float m = fmaxf(red[tid], red[tid + 32]);
        atomicMax(&g_cmbits[layer][tid], __float_as_uint(m));
    }
}

// ---------------------------------------------------------------------------
// 2) zs = dinv ⊙ (x @ W1 + b1)   ; fp32 g_zs + colmax[0]
// ---------------------------------------------------------------------------
__global__ __launch_bounds__(256) void z1_kernel(const float* __restrict__ x,
                                                 const float* __restrict__ W1,
                                                 const float* __restrict__ b1) {
    __shared__ float Ws[IND * HID];
    __shared__ float xs[8][IND];
    int tid = threadIdx.x;
    int row0 = blockIdx.x * 8;
    for (int i = tid; i < IND * HID; i += 256) Ws[i] = W1[i];
    for (int i = tid; i < 8 * IND; i += 256)
        xs[i >> 7][i & 127] = x[(size_t)(row0 + (i >> 7)) * IND + (i & 127)];
    __syncthreads();
    int r = tid >> 5, c = tid & 31;
    float acc = b1[c];
#pragma unroll 8
    for (int k = 0; k < IND; k++) acc += xs[r][k] * Ws[k * HID + c];
    int row = row0 + r;
    float v = g_dinv[row] * acc;
    g_zs[row * HID + c] = v;
    colmax_update(v, tid, c, 0);
}

// ---------------------------------------------------------------------------
// 4) zs = dinv ⊙ (h @ W2 + b2)   ; fp32 g_zs + colmax[1]
// ---------------------------------------------------------------------------
__global__ __launch_bounds__(256) void z2_kernel(const float* __restrict__ W2,
                                                 const float* __restrict__ b2) {
    __shared__ float Ws[HID * HID];
    __shared__ float hs[8][HID];
    int tid = threadIdx.x;
    int row0 = blockIdx.x * 8;
    for (int i = tid; i < HID * HID; i += 256) Ws[i] = W2[i];
    for (int i = tid; i < 8 * HID; i += 256)
        hs[i >> 5][i & 31] = g_h[(size_t)(row0 + (i >> 5)) * HID + (i & 31)];
    __syncthreads();
    int r = tid >> 5, c = tid & 31;
    float acc = b2[c];
#pragma unroll
    for (int k = 0; k < HID; k++) acc += hs[r][k] * Ws[k * HID + c];
    int row = row0 + r;
    float v = g_dinv[row] * acc;
    g_zs[row * HID + c] = v;
    colmax_update(v, tid, c, 1);
}

// ---------------------------------------------------------------------------
// Quantize+transpose: g_zqT[c][j] = round(zs[j][c] * 127/cmax_c)
// ---------------------------------------------------------------------------
__global__ __launch_bounds__(256) void quantT_kernel(int layer) {
    __shared__ float tile[128][HID + 1];
    __shared__ float rcp_s[HID];
    int tid = threadIdx.x;
    int row0 = blockIdx.x * 128;
    if (tid < HID)
        rcp_s[tid] = 127.f / fmaxf(__uint_as_float(g_cmbits[layer][tid]), 1e-20f);
    for (int i = tid; i < 128 * 8; i += 256) {
        int r = i >> 3, c4 = (i & 7) << 2;
        float4 v = *reinterpret_cast<const float4*>(&g_zs[(size_t)(row0 + r) * HID + c4]);
        tile[r][c4 + 0] = v.x; tile[r][c4 + 1] = v.y;
        tile[r][c4 + 2] = v.z; tile[r][c4 + 3] = v.w;
    }
    __syncthreads();
    int col = tid >> 3, jb = (tid & 7) * 16;
    float rcp = rcp_s[col];
    signed char q[16];
#pragma unroll
    for (int j = 0; j < 16; j++)
        q[j] = (signed char)__float2int_rn(tile[jb + j][col] * rcp);
    *reinterpret_cast<int4*>(&g_zqT[(size_t)col * Nn + row0 + jb]) =
        *reinterpret_cast<int4*>(q);
}

// ---------------------------------------------------------------------------
// 3+5) s32 partials of adjq @ zqT^T via mma m16n8k32 u8.s8, 3-stage cp.async.
//      grid = 64 M-tiles * KSPLIT = 512 blocks, 128 threads.
// ---------------------------------------------------------------------------
__global__ __launch_bounds__(128) void spmm_mma_kernel() {
    __shared__ __align__(16) unsigned char smem[NSTAGE * STAGE];  // 38400 B

    const int tid  = threadIdx.x;
    const int wid  = tid >> 5;
    const int lane = tid & 31;
    const int mb   = blockIdx.x >> 3;
    const int ks   = blockIdx.x & (KSPLIT - 1);
    const int row0 = mb * BM;
    const int k0   = ks * KCHUNK;

    const uint32_t sbase = smem_u32(smem);
    const int m0 = wid * 32;

    // fragment address invariants (b16 view of s8 tiles)
    const uint32_t aFragInv = (uint32_t)((m0 + (lane & 15)) * APITCH + (lane >> 4) * 16);
    const uint32_t bFragInv = (uint32_t)((lane & 7) * APITCH + ((lane >> 3) & 1) * 16);

    int c[2][4][4];
#pragma unroll
    for (int mt = 0; mt < 2; mt++)
#pragma unroll
        for (int nt = 0; nt < 4; nt++)
#pragma unroll
            for (int j = 0; j < 4; j++) c[mt][nt][j] = 0;

    auto issue = [&](int t) {
        const uint32_t dst = sbase + (uint32_t)((t % NSTAGE) * STAGE);
        const size_t koff = (size_t)k0 + (size_t)t * BKB;
        const unsigned char* aS = g_adjq + (size_t)(row0 + tid) * Nn + koff;
#pragma unroll
        for (int ch = 0; ch < 4; ch++)
            cp16(dst + tid * APITCH + ch * 16, aS + ch * 16);
        const int brow = tid >> 2, bch = tid & 3;
        cp16(dst + ASZ + brow * APITCH + bch * 16,
             g_zqT + (size_t)brow * Nn + koff + bch * 16);
        asm volatile("cp.async.commit_group;" ::: "memory");
    };

    issue(0);
    issue(1);

    for (int t = 0; t < NTILE; t++) {
        if (t <= NTILE - 2)
            asm volatile("cp.async.wait_group 1;" ::: "memory");
        else
            asm volatile("cp.async.wait_group 0;" ::: "memory");
        __syncthreads();
        if (t + 2 < NTILE) issue(t + 2);

        const uint32_t aBase = sbase + (uint32_t)((t % NSTAGE) * STAGE);
        const uint32_t bBase = aBase + ASZ;
#pragma unroll
        for (int kk = 0; kk < 2; kk++) {
            uint32_t a[2][4];
#pragma unroll
            for (int mt = 0; mt < 2; mt++) {
                asm volatile(
                    "ldmatrix.sync.aligned.m8n8.x4.shared.b16 {%0,%1,%2,%3}, [%4];"
                    : "=r"(a[mt][0]), "=r"(a[mt][1]), "=r"(a[mt][2]), "=r"(a[mt][3])
                    : "r"(aBase + aFragInv + mt * 16 * APITCH + kk * 32));
            }
            uint32_t b[4][2];
#pragma unroll
            for (int nt = 0; nt < 4; nt++) {
                asm volatile(
                    "ldmatrix.sync.aligned.m8n8.x2.shared.b16 {%0,%1}, [%2];"
                    : "=r"(b[nt][0]), "=r"(b[nt][1])
                    : "r"(bBase + bFragInv + nt * 8 * APITCH + kk * 32));
            }
#pragma unroll
            for (int mt = 0; mt < 2; mt++)
#pragma unroll
                for (int nt = 0; nt < 4; nt++) {
                    asm volatile(
                        "mma.sync.aligned.m16n8k32.row.col.s32.u8.s8.s32 "
                        "{%0,%1,%2,%3}, {%4,%5,%6,%7}, {%8,%9}, {%0,%1,%2,%3};"
                        : "+r"(c[mt][nt][0]), "+r"(c[mt][nt][1]),
                          "+r"(c[mt][nt][2]), "+r"(c[mt][nt][3])
                        : "r"(a[mt][0]), "r"(a[mt][1]), "r"(a[mt][2]), "r"(a[mt][3]),
                          "r"(b[nt][0]), "r"(b[nt][1]));
                }
        }
        __syncthreads();
    }

    // write s32 partials (same m16n8 C lane layout as f32 HMMA)
    int* pp = g_part + (size_t)ks * Nn * HID;
    const int g  = lane >> 2;
    const int tg = lane & 3;
#pragma unroll
    for (int mt = 0; mt < 2; mt++) {
        const int rbase = row0 + m0 + mt * 16;
#pragma unroll
        for (int nt = 0; nt < 4; nt++) {
            const int col = nt * 8 + tg * 2;
            *reinterpret_cast<int2*>(&pp[(size_t)(rbase + g) * HID + col]) =
                make_int2(c[mt][nt][0], c[mt][nt][1]);
            *reinterpret_cast<int2*>(&pp[(size_t)(rbase + g + 8) * HID + col]) =
                make_int2(c[mt][nt][2], c[mt][nt][3]);
        }
    }
}

// ---------------------------------------------------------------------------
// Epilogue L1: h = relu(dinv ⊙ (dequant(sum partials) + zs))
// ---------------------------------------------------------------------------
__global__ __launch_bounds__(256) void epilogue1_kernel() {
    int idx4 = blockIdx.x * 256 + threadIdx.x;
    int row = idx4 >> 3;
    int c0 = (idx4 & 7) << 2;
    int4 S = reinterpret_cast<const int4*>(g_part)[idx4];
#pragma unroll
    for (int p = 1; p < KSPLIT; p++) {
        int4 v = reinterpret_cast<const int4*>(g_part + (size_t)p * Nn * HID)[idx4];
        S.x += v.x; S.y += v.y; S.z += v.z; S.w += v.w;
    }
    float4 zs = reinterpret_cast<const float4*>(g_zs)[idx4];
    float di = g_dinv[row];
    const float inv = 1.0f / 32385.0f;  // 1/(127*255)
    float f0 = __uint_as_float(g_cmbits[0][c0 + 0]) * inv;
    float f1 = __uint_as_float(g_cmbits[0][c0 + 1]) * inv;
    float f2 = __uint_as_float(g_cmbits[0][c0 + 2]) * inv;
    float f3 = __uint_as_float(g_cmbits[0][c0 + 3]) * inv;
    float4 o;
    o.x = fmaxf(di * (S.x * f0 + zs.x), 0.f);
    o.y = fmaxf(di * (S.y * f1 + zs.y), 0.f);
    o.z = fmaxf(di * (S.z * f2 + zs.z), 0.f);
    o.w = fmaxf(di * (S.w * f3 + zs.w), 0.f);
    reinterpret_cast<float4*>(g_h)[idx4] = o;
}

// ---------------------------------------------------------------------------
// Epilogue L2 + final: logits = relu(dinv ⊙ (dequant + zs)) @ W3 + b3
// ---------------------------------------------------------------------------
__global__ __launch_bounds__(256) void epilogue_final_kernel(const float* __restrict__ W3,
                                                             const float* __restrict__ b3,
                                                             float* __restrict__ out) {
    int tid = threadIdx.x;
    int idx4 = blockIdx.x * 256 + tid;
    int row = idx4 >> 3;
    int c0 = (idx4 & 7) << 2;
    int4 S = reinterpret_cast<const int4*>(g_part)[idx4];
#pragma unroll
    for (int p = 1; p < KSPLIT; p++) {
        int4 v = reinterpret_cast<const int4*>(g_part + (size_t)p * Nn * HID)[idx4];
        S.x += v.x; S.y += v.y; S.z += v.z; S.w += v.w;
    }
    float4 zs = reinterpret_cast<const float4*>(g_zs)[idx4];
    float di = g_dinv[row];
    const float inv = 1.0f / 32385.0f;
    float f0 = __uint_as_float(g_cmbits[1][c0 + 0]) * inv;
    float f1 = __uint_as_float(g_cmbits[1][c0 + 1]) * inv;
    float f2 = __uint_as_float(g_cmbits[1][c0 + 2]) * inv;
    float f3 = __uint_as_float(g_cmbits[1][c0 + 3]) * inv;
    float h0 = fmaxf(di * (S.x * f0 + zs.x), 0.f);
    float h1 = fmaxf(di * (S.y * f1 + zs.y), 0.f);
    float h2 = fmaxf(di * (S.z * f2 + zs.z), 0.f);
    float h3 = fmaxf(di * (S.w * f3 + zs.w), 0.f);
    float v = h0 * W3[c0] + h1 * W3[c0 + 1] + h2 * W3[c0 + 2] + h3 * W3[c0 + 3];
#pragma unroll
    for (int o = 4; o; o >>= 1) v += __shfl_xor_sync(0xffffffffu, v, o);
    if ((tid & 7) == 0) out[row] = v + b3[0];
}

// ---------------------------------------------------------------------------
extern "C" void kernel_launch(void* const* d_in, const int* in_sizes, int n_in,
                              void* d_out, int out_size) {
    const float* x   = (const float*)d_in[0];
    const float* adj = (const float*)d_in[1];
    const float* W1  = (const float*)d_in[2];
    const float* b1  = (const float*)d_in[3];
    const float* W2  = (const float*)d_in[4];
    const float* b2  = (const float*)d_in[5];
    const float* W3  = (const float*)d_in[6];
    const float* b3  = (const float*)d_in[7];
    float* out = (float*)d_out;

    degree_convert_kernel<<<Nn, 256>>>(adj);
    z1_kernel<<<Nn / 8, 256>>>(x, W1, b1);
    quantT_kernel<<<Nn / 128, 256>>>(0);
    spmm_mma_kernel<<<(Nn / BM) * KSPLIT, 128>>>();   // layer 1 partials (s32)
    epilogue1_kernel<<<Nn * HID / 4 / 256, 256>>>();  // -> g_h
    z2_kernel<<<Nn / 8, 256>>>(W2, b2);               // g_h -> g_zs + colmax[1]
    quantT_kernel<<<Nn / 128, 256>>>(1);
    spmm_mma_kernel<<<(Nn / BM) * KSPLIT, 128>>>();   // layer 2 partials (s32)
    epilogue_final_kernel<<<Nn * HID / 4 / 256, 256>>>(W3, b3, out);
}

// round 6
// speedup vs baseline: 1.0525x; 1.0525x over previous
#include <cuda_runtime.h>
#include <cstdint>

#define Nn     8192
#define IND    128
#define HID    32
#define BM     128
#define BKB    64                 // k bytes (= elements, u8) per tile
#define KSPLIT 8
#define KCHUNK (Nn / KSPLIT)      // 1024
#define NTILE  (KCHUNK / BKB)     // 16
#define APITCH 80                 // padded row pitch (bytes), conflict-free
#define ASZ    (BM * APITCH)      // 10240
#define BSZ    (HID * APITCH)     // 2560
#define STAGE  (ASZ + BSZ)        // 12800
#define NSTAGE 3

// Scratch (static device arrays only; no allocations)
__device__ unsigned char g_adjq[(size_t)Nn * Nn];     // u8 adj (64 MB)
__device__ float         g_dinv[Nn];
__device__ float         g_zs[Nn * HID];              // fp32 zs (exact self-loop term)
__device__ signed char   g_zqT[(size_t)HID * Nn];     // s8 zs transposed [c][j]
__device__ int           g_part[(size_t)KSPLIT * Nn * HID];  // s32 partials
__device__ unsigned      g_cmbits[2][HID];            // per-column absmax (as uint bits)

// ---------------------------------------------------------------------------
__device__ __forceinline__ uint32_t smem_u32(const void* p) {
    uint32_t a;
    asm("{ .reg .u64 t; cvta.to.shared.u64 t, %1; cvt.u32.u64 %0, t; }" : "=r"(a) : "l"(p));
    return a;
}
__device__ __forceinline__ void cp16(uint32_t dst, const void* src) {
    asm volatile("cp.async.ca.shared.global [%0], [%1], 16;" :: "r"(dst), "l"(src));
}

// ---------------------------------------------------------------------------
// 1) degree + u8 convert: dinv = rsqrt(max(1,1+rowsum)); adjq = round(adj*255)
// ---------------------------------------------------------------------------
__global__ __launch_bounds__(256) void degree_convert_kernel(const float* __restrict__ adj) {
    if (blockIdx.x == 0 && threadIdx.x < 2 * HID)
        reinterpret_cast<unsigned*>(g_cmbits)[threadIdx.x] = 0u;
    int row = blockIdx.x;
    const float4* rp = reinterpret_cast<const float4*>(adj + (size_t)row * Nn);
    uchar4* qp = reinterpret_cast<uchar4*>(g_adjq + (size_t)row * Nn);
    float s = 0.f;
    for (int i = threadIdx.x; i < Nn / 4; i += 256) {
        float4 v = rp[i];
        s += (v.x + v.y) + (v.z + v.w);
        uchar4 q;
        q.x = (unsigned char)__float2int_rn(v.x * 255.f);
        q.y = (unsigned char)__float2int_rn(v.y * 255.f);
        q.z = (unsigned char)__float2int_rn(v.z * 255.f);
        q.w = (unsigned char)__float2int_rn(v.w * 255.f);
        qp[i] = q;
    }
#pragma unroll
    for (int o = 16; o; o >>= 1) s += __shfl_down_sync(0xffffffffu, s, o);
    __shared__ float ws[8];
    int lane = threadIdx.x & 31, w = threadIdx.x >> 5;
    if (lane == 0) ws[w] = s;
    __syncthreads();
    if (threadIdx.x == 0) {
        float d = 1.0f;  // self loop
#pragma unroll
        for (int i = 0; i < 8; i++) d += ws[i];
        d = fmaxf(d, 1.0f);
        g_dinv[row] = rsqrtf(d);
    }
}

// ---------------------------------------------------------------------------
// 2) zs = dinv ⊙ (x @ W1 + b1)   ; fp32 g_zs + colmax[0]
// ---------------------------------------------------------------------------
__global__ __launch_bounds__(256) void z1_kernel(const float* __restrict__ x,
                                                 const float* __restrict__ W1,
                                                 const float* __restrict__ b1) {
    __shared__ float Ws[IND * HID];
    __shared__ float xs[8][IND];
    __shared__ float red[256];
    int tid = threadIdx.x;
    int row0 = blockIdx.x * 8;
    for (int i = tid; i < IND * HID; i += 256) Ws[i] = W1[i];
    for (int i = tid; i < 8 * IND; i += 256)
        xs[i >> 7][i & 127] = x[(size_t)(row0 + (i >> 7)) * IND + (i & 127)];
    __syncthreads();
    int r = tid >> 5, c = tid & 31;
    float acc = b1[c];
#pragma unroll 8
    for (int k = 0; k < IND; k++) acc += xs[r][k] * Ws[k * HID + c];
    int row = row0 + r;
    float v = g_dinv[row] * acc;
    g_zs[row * HID + c] = v;
    // colmax reduce
    red[tid] = fabsf(v);
    __syncthreads();
    if (tid < 128) red[tid] = fmaxf(red[tid], red[tid + 128]);
    __syncthreads();
    if (tid < 64) red[tid] = fmaxf(red[tid], red[tid + 64]);
    __syncthreads();
    if (tid < 32) atomicMax(&g_cmbits[0][tid], __float_as_uint(fmaxf(red[tid], red[tid + 32])));
}

// ---------------------------------------------------------------------------
// Quantize+transpose: g_zqT[c][j] = round(zs[j][c] * 127/cmax_c)
// ---------------------------------------------------------------------------
__global__ __launch_bounds__(256) void quantT_kernel(int layer) {
    __shared__ float tile[128][HID + 1];
    __shared__ float rcp_s[HID];
    int tid = threadIdx.x;
    int row0 = blockIdx.x * 128;
    if (tid < HID)
        rcp_s[tid] = 127.f / fmaxf(__uint_as_float(g_cmbits[layer][tid]), 1e-20f);
    for (int i = tid; i < 128 * 8; i += 256) {
        int r = i >> 3, c4 = (i & 7) << 2;
        float4 v = *reinterpret_cast<const float4*>(&g_zs[(size_t)(row0 + r) * HID + c4]);
        tile[r][c4 + 0] = v.x; tile[r][c4 + 1] = v.y;
        tile[r][c4 + 2] = v.z; tile[r][c4 + 3] = v.w;
    }
    __syncthreads();
    int col = tid >> 3, jb = (tid & 7) * 16;
    float rcp = rcp_s[col];
    signed char q[16];
#pragma unroll
    for (int j = 0; j < 16; j++)
        q[j] = (signed char)__float2int_rn(tile[jb + j][col] * rcp);
    *reinterpret_cast<int4*>(&g_zqT[(size_t)col * Nn + row0 + jb]) =
        *reinterpret_cast<int4*>(q);
}

// ---------------------------------------------------------------------------
// 3+5) s32 partials of adjq @ zqT^T via mma m16n8k32 u8.s8.
//      256 threads (8 warps, 16 rows each), 3-stage cp.async, grid 512.
// ---------------------------------------------------------------------------
__global__ __launch_bounds__(256) void spmm_mma_kernel() {
    __shared__ __align__(16) unsigned char smem[NSTAGE * STAGE];  // 38400 B

    const int tid  = threadIdx.x;
    const int wid  = tid >> 5;
    const int lane = tid & 31;
    const int mb   = blockIdx.x >> 3;
    const int ks   = blockIdx.x & (KSPLIT - 1);
    const int row0 = mb * BM;
    const int k0   = ks * KCHUNK;

    const uint32_t sbase = smem_u32(smem);
    const int m0 = wid * 16;

    // fragment address invariants (b16 view of s8 tiles)
    const uint32_t aFragInv = (uint32_t)((m0 + (lane & 15)) * APITCH + (lane >> 4) * 16);
    const uint32_t bFragInv = (uint32_t)((lane & 7) * APITCH + ((lane >> 3) & 1) * 16);

    int c[4][4];
#pragma unroll
    for (int nt = 0; nt < 4; nt++)
#pragma unroll
        for (int j = 0; j < 4; j++) c[nt][j] = 0;

    auto issue = [&](int t) {
        const uint32_t dst = sbase + (uint32_t)((t % NSTAGE) * STAGE);
        const size_t koff = (size_t)k0 + (size_t)t * BKB;
        // A: 128 rows x 4 chunks of 16B = 512 chunks, 2 per thread
#pragma unroll
        for (int i = 0; i < 2; i++) {
            const int ci = tid + i * 256;
            const int r = ci >> 2, ch = ci & 3;
            cp16(dst + r * APITCH + ch * 16,
                 g_adjq + (size_t)(row0 + r) * Nn + koff + ch * 16);
        }
        // B: 32 rows x 4 chunks = 128 chunks (first 128 threads)
        if (tid < 128) {
            const int r = tid >> 2, ch = tid & 3;
            cp16(dst + ASZ + r * APITCH + ch * 16,
                 g_zqT + (size_t)r * Nn + koff + ch * 16);
        }
        asm volatile("cp.async.commit_group;" ::: "memory");
    };

    issue(0);
    issue(1);

    for (int t = 0; t < NTILE; t++) {
        if (t <= NTILE - 2)
            asm volatile("cp.async.wait_group 1;" ::: "memory");
        else
            asm volatile("cp.async.wait_group 0;" ::: "memory");
        __syncthreads();
        if (t + 2 < NTILE) issue(t + 2);

        const uint32_t aBase = sbase + (uint32_t)((t % NSTAGE) * STAGE);
        const uint32_t bBase = aBase + ASZ;
#pragma unroll
        for (int kk = 0; kk < 2; kk++) {
            uint32_t a[4];
            asm volatile(
                "ldmatrix.sync.aligned.m8n8.x4.shared.b16 {%0,%1,%2,%3}, [%4];"
                : "=r"(a[0]), "=r"(a[1]), "=r"(a[2]), "=r"(a[3])
                : "r"(aBase + aFragInv + kk * 32));
            uint32_t b[4][2];
#pragma unroll
            for (int nt = 0; nt < 4; nt++) {
                asm volatile(
                    "ldmatrix.sync.aligned.m8n8.x2.shared.b16 {%0,%1}, [%2];"
                    : "=r"(b[nt][0]), "=r"(b[nt][1])
                    : "r"(bBase + bFragInv + nt * 8 * APITCH + kk * 32));
            }
#pragma unroll
            for (int nt = 0; nt < 4; nt++) {
                asm volatile(
                    "mma.sync.aligned.m16n8k32.row.col.s32.u8.s8.s32 "
                    "{%0,%1,%2,%3}, {%4,%5,%6,%7}, {%8,%9}, {%0,%1,%2,%3};"
                    : "+r"(c[nt][0]), "+r"(c[nt][1]), "+r"(c[nt][2]), "+r"(c[nt][3])
                    : "r"(a[0]), "r"(a[1]), "r"(a[2]), "r"(a[3]),
                      "r"(b[nt][0]), "r"(b[nt][1]));
            }
        }
        __syncthreads();
    }

    // write s32 partials (m16n8 C lane layout)
    int* pp = g_part + (size_t)ks * Nn * HID;
    const int g  = lane >> 2;
    const int tg = lane & 3;
    const int rbase = row0 + m0;
#pragma unroll
    for (int nt = 0; nt < 4; nt++) {
        const int col = nt * 8 + tg * 2;
        *reinterpret_cast<int2*>(&pp[(size_t)(rbase + g) * HID + col]) =
            make_int2(c[nt][0], c[nt][1]);
        *reinterpret_cast<int2*>(&pp[(size_t)(rbase + g + 8) * HID + col]) =
            make_int2(c[nt][2], c[nt][3]);
    }
}

// ---------------------------------------------------------------------------
// Fused: h = relu(dinv⊙(dequant(Σpartials)+zs));  zs' = dinv⊙(h@W2+b2); colmax[1]
//        32 rows per block, 256 threads.
// ---------------------------------------------------------------------------
__global__ __launch_bounds__(256) void epi1_z2_kernel(const float* __restrict__ W2,
                                                      const float* __restrict__ b2) {
    __shared__ float hs[32][HID + 1];
    __shared__ float W2s[HID * HID];
    __shared__ unsigned cm[HID];
    int tid = threadIdx.x;
    int r = tid >> 3;             // 0..31
    int c0 = (tid & 7) << 2;      // 0,4,..28
    int row = blockIdx.x * 32 + r;
    int idx4 = (row * HID + c0) >> 2;

    for (int i = tid; i < HID * HID; i += 256) W2s[i] = W2[i];
    if (tid < HID) cm[tid] = 0u;

    int4 S = reinterpret_cast<const int4*>(g_part)[idx4];
#pragma unroll
    for (int p = 1; p < KSPLIT; p++) {
        int4 v = reinterpret_cast<const int4*>(g_part + (size_t)p * Nn * HID)[idx4];
        S.x += v.x; S.y += v.y; S.z += v.z; S.w += v.w;
    }
    float4 zs = reinterpret_cast<const float4*>(g_zs)[idx4];
    float di = g_dinv[row];
    const float inv = 1.0f / 32385.0f;  // 1/(127*255)
    float f0 = __uint_as_float(g_cmbits[0][c0 + 0]) * inv;
    float f1 = __uint_as_float(g_cmbits[0][c0 + 1]) * inv;
    float f2 = __uint_as_float(g_cmbits[0][c0 + 2]) * inv;
    float f3 = __uint_as_float(g_cmbits[0][c0 + 3]) * inv;
    hs[r][c0 + 0] = fmaxf(di * (S.x * f0 + zs.x), 0.f);
    hs[r][c0 + 1] = fmaxf(di * (S.y * f1 + zs.y), 0.f);
    hs[r][c0 + 2] = fmaxf(di * (S.z * f2 + zs.z), 0.f);
    hs[r][c0 + 3] = fmaxf(di * (S.w * f3 + zs.w), 0.f);
    __syncthreads();

    // z[r][c0..c0+3] = dinv * (hs[r,:] @ W2[:,c] + b2[c])
    float acc[4] = { b2[c0], b2[c0 + 1], b2[c0 + 2], b2[c0 + 3] };
#pragma unroll
    for (int k = 0; k < HID; k++) {
        float hv = hs[r][k];
        acc[0] += hv * W2s[k * HID + c0 + 0];
        acc[1] += hv * W2s[k * HID + c0 + 1];
        acc[2] += hv * W2s[k * HID + c0 + 2];
        acc[3] += hv * W2s[k * HID + c0 + 3];
    }
    float4 o;
    o.x = di * acc[0]; o.y = di * acc[1]; o.z = di * acc[2]; o.w = di * acc[3];
    reinterpret_cast<float4*>(g_zs)[idx4] = o;
    // block-local colmax then one global atomic per col
    atomicMax(&cm[c0 + 0], __float_as_uint(fabsf(o.x)));
    atomicMax(&cm[c0 + 1], __float_as_uint(fabsf(o.y)));
    atomicMax(&cm[c0 + 2], __float_as_uint(fabsf(o.z)));
    atomicMax(&cm[c0 + 3], __float_as_uint(fabsf(o.w)));
    __syncthreads();
    if (tid < HID) atomicMax(&g_cmbits[1][tid], cm[tid]);
}

// ---------------------------------------------------------------------------
// Epilogue L2 + final: logits = relu(dinv⊙(dequant+zs)) @ W3 + b3
// ---------------------------------------------------------------------------
__global__ __launch_bounds__(256) void epilogue_final_kernel(const float* __restrict__ W3,
                                                             const float* __restrict__ b3,
                                                             float* __restrict__ out) {
    int tid = threadIdx.x;
    int idx4 = blockIdx.x * 256 + tid;
    int row = idx4 >> 3;
    int c0 = (idx4 & 7) << 2;
    int4 S = reinterpret_cast<const int4*>(g_part)[idx4];
#pragma unroll
    for (int p = 1; p < KSPLIT; p++) {
        int4 v = reinterpret_cast<const int4*>(g_part + (size_t)p * Nn * HID)[idx4];
        S.x += v.x; S.y += v.y; S.z += v.z; S.w += v.w;
    }
    float4 zs = reinterpret_cast<const float4*>(g_zs)[idx4];
    float di = g_dinv[row];
    const float inv = 1.0f / 32385.0f;
    float f0 = __uint_as_float(g_cmbits[1][c0 + 0]) * inv;
    float f1 = __uint_as_float(g_cmbits[1][c0 + 1]) * inv;
    float f2 = __uint_as_float(g_cmbits[1][c0 + 2]) * inv;
    float f3 = __uint_as_float(g_cmbits[1][c0 + 3]) * inv;
    float h0 = fmaxf(di * (S.x * f0 + zs.x), 0.f);
    float h1 = fmaxf(di * (S.y * f1 + zs.y), 0.f);
    float h2 = fmaxf(di * (S.z * f2 + zs.z), 0.f);
    float h3 = fmaxf(di * (S.w * f3 + zs.w), 0.f);
    float v = h0 * W3[c0] + h1 * W3[c0 + 1] + h2 * W3[c0 + 2] + h3 * W3[c0 + 3];
#pragma unroll
    for (int o = 4; o; o >>= 1) v += __shfl_xor_sync(0xffffffffu, v, o);
    if ((tid & 7) == 0) out[row] = v + b3[0];
}

// ---------------------------------------------------------------------------
extern "C" void kernel_launch(void* const* d_in, const int* in_sizes, int n_in,
                              void* d_out, int out_size) {
    const float* x   = (const float*)d_in[0];
    const float* adj = (const float*)d_in[1];
    const float* W1  = (const float*)d_in[2];
    const float* b1  = (const float*)d_in[3];
    const float* W2  = (const float*)d_in[4];
    const float* b2  = (const float*)d_in[5];
    const float* W3  = (const float*)d_in[6];
    const float* b3  = (const float*)d_in[7];
    float* out = (float*)d_out;

    degree_convert_kernel<<<Nn, 256>>>(adj);
    z1_kernel<<<Nn / 8, 256>>>(x, W1, b1);
    quantT_kernel<<<Nn / 128, 256>>>(0);
    spmm_mma_kernel<<<(Nn / BM) * KSPLIT, 256>>>();   // layer 1 partials (s32)
    epi1_z2_kernel<<<Nn / 32, 256>>>(W2, b2);         // h + z2 fused -> g_zs
    quantT_kernel<<<Nn / 128, 256>>>(1);
    spmm_mma_kernel<<<(Nn / BM) * KSPLIT, 256>>>();   // layer 2 partials (s32)
    epilogue_final_kernel<<<Nn * HID / 4 / 256, 256>>>(W3, b3, out);
}

// round 7
// speedup vs baseline: 1.1152x; 1.0596x over previous
#include <cuda_runtime.h>
#include <cstdint>

#define Nn     8192
#define IND    128
#define HID    32
#define BM     128
#define KSPLIT 16
#define KCHUNK (Nn / KSPLIT)      // 512
#define NTILE  (KCHUNK / 64)      // 8 tiles of k=64

// Scratch (static device arrays only; no allocations)
__device__ unsigned char g_adjq[(size_t)Nn * Nn];     // u8 adj (64 MB)
__device__ float         g_dinv[Nn];
__device__ float         g_zs[Nn * HID];              // fp32 zs (exact self-loop term)
__device__ signed char   g_zqT[(size_t)HID * Nn];     // s8 zs transposed [c][j]
__device__ int           g_part[(size_t)KSPLIT * Nn * HID];  // s32 partials (16 MB)
__device__ unsigned      g_cmbits[2][HID];            // per-column absmax (as uint bits)

// ---------------------------------------------------------------------------
__device__ __forceinline__ uint32_t smem_u32(const void* p) {
    uint32_t a;
    asm("{ .reg .u64 t; cvta.to.shared.u64 t, %1; cvt.u32.u64 %0, t; }" : "=r"(a) : "l"(p));
    return a;
}
__device__ __forceinline__ void cp16(uint32_t dst, const void* src) {
    asm volatile("cp.async.cg.shared.global [%0], [%1], 16;" :: "r"(dst), "l"(src));
}

// ---------------------------------------------------------------------------
// 1) degree + u8 convert: dinv = rsqrt(max(1,1+rowsum)); adjq = round(adj*255)
// ---------------------------------------------------------------------------
__global__ __launch_bounds__(256) void degree_convert_kernel(const float* __restrict__ adj) {
    if (blockIdx.x == 0 && threadIdx.x < 2 * HID)
        reinterpret_cast<unsigned*>(g_cmbits)[threadIdx.x] = 0u;
    int row = blockIdx.x;
    const float4* rp = reinterpret_cast<const float4*>(adj + (size_t)row * Nn);
    uchar4* qp = reinterpret_cast<uchar4*>(g_adjq + (size_t)row * Nn);
    float s = 0.f;
    for (int i = threadIdx.x; i < Nn / 4; i += 256) {
        float4 v = rp[i];
        s += (v.x + v.y) + (v.z + v.w);
        uchar4 q;
        q.x = (unsigned char)__float2int_rn(v.x * 255.f);
        q.y = (unsigned char)__float2int_rn(v.y * 255.f);
        q.z = (unsigned char)__float2int_rn(v.z * 255.f);
        q.w = (unsigned char)__float2int_rn(v.w * 255.f);
        qp[i] = q;
    }
#pragma unroll
    for (int o = 16; o; o >>= 1) s += __shfl_down_sync(0xffffffffu, s, o);
    __shared__ float ws[8];
    int lane = threadIdx.x & 31, w = threadIdx.x >> 5;
    if (lane == 0) ws[w] = s;
    __syncthreads();
    if (threadIdx.x == 0) {
        float d = 1.0f;  // self loop
#pragma unroll
        for (int i = 0; i < 8; i++) d += ws[i];
        d = fmaxf(d, 1.0f);
        g_dinv[row] = rsqrtf(d);
    }
}

// ---------------------------------------------------------------------------
// 2) zs = dinv ⊙ (x @ W1 + b1)   ; fp32 g_zs + colmax[0]
// ---------------------------------------------------------------------------
__global__ __launch_bounds__(256) void z1_kernel(const float* __restrict__ x,
                                                 const float* __restrict__ W1,
                                                 const float* __restrict__ b1) {
    __shared__ float Ws[IND * HID];
    __shared__ float xs[8][IND];
    __shared__ float red[256];
    int tid = threadIdx.x;
    int row0 = blockIdx.x * 8;
    for (int i = tid; i < IND * HID; i += 256) Ws[i] = W1[i];
    for (int i = tid; i < 8 * IND; i += 256)
        xs[i >> 7][i & 127] = x[(size_t)(row0 + (i >> 7)) * IND + (i & 127)];
    __syncthreads();
    int r = tid >> 5, c = tid & 31;
    float acc = b1[c];
#pragma unroll 8
    for (int k = 0; k < IND; k++) acc += xs[r][k] * Ws[k * HID + c];
    int row = row0 + r;
    float v = g_dinv[row] * acc;
    g_zs[row * HID + c] = v;
    red[tid] = fabsf(v);
    __syncthreads();
    if (tid < 128) red[tid] = fmaxf(red[tid], red[tid + 128]);
    __syncthreads();
    if (tid < 64) red[tid] = fmaxf(red[tid], red[tid + 64]);
    __syncthreads();
    if (tid < 32) atomicMax(&g_cmbits[0][tid], __float_as_uint(fmaxf(red[tid], red[tid + 32])));
}

// ---------------------------------------------------------------------------
// Quantize+transpose: g_zqT[c][j] = round(zs[j][c] * 127/cmax_c)
// ---------------------------------------------------------------------------
__global__ __launch_bounds__(256) void quantT_kernel(int layer) {
    __shared__ float tile[128][HID + 1];
    __shared__ float rcp_s[HID];
    int tid = threadIdx.x;
    int row0 = blockIdx.x * 128;
    if (tid < HID)
        rcp_s[tid] = 127.f / fmaxf(__uint_as_float(g_cmbits[layer][tid]), 1e-20f);
    for (int i = tid; i < 128 * 8; i += 256) {
        int r = i >> 3, c4 = (i & 7) << 2;
        float4 v = *reinterpret_cast<const float4*>(&g_zs[(size_t)(row0 + r) * HID + c4]);
        tile[r][c4 + 0] = v.x; tile[r][c4 + 1] = v.y;
        tile[r][c4 + 2] = v.z; tile[r][c4 + 3] = v.w;
    }
    __syncthreads();
    int col = tid >> 3, jb = (tid & 7) * 16;
    float rcp = rcp_s[col];
    signed char q[16];
#pragma unroll
    for (int j = 0; j < 16; j++)
        q[j] = (signed char)__float2int_rn(tile[jb + j][col] * rcp);
    *reinterpret_cast<int4*>(&g_zqT[(size_t)col * Nn + row0 + jb]) =
        *reinterpret_cast<int4*>(q);
}

// ---------------------------------------------------------------------------
// 3+5) s32 partials of adjq @ zqT^T via mma m16n8k32 u8.s8.
//      A: direct LDG fragments (no smem). B: whole 32x512 K-chunk in smem,
//      XOR-swizzled, loaded once -> ZERO barriers in main loop.
//      grid = 64 M-tiles * 16 ksplits = 1024 blocks, 256 threads, all resident.
// ---------------------------------------------------------------------------
__global__ __launch_bounds__(256) void spmm_mma_kernel() {
    __shared__ __align__(16) unsigned char sB[HID * KCHUNK];  // 16 KB

    const int tid  = threadIdx.x;
    const int wid  = tid >> 5;
    const int lane = tid & 31;
    const int mb   = blockIdx.x >> 4;
    const int ks   = blockIdx.x & (KSPLIT - 1);
    const int row0 = mb * BM;
    const int k0   = ks * KCHUNK;
    const uint32_t sbase = smem_u32(sB);
    const int m0 = wid * 16;

    // ---- load full B chunk: 32 rows x 32 chunks of 16B, swizzle chunk^row ----
#pragma unroll
    for (int i = 0; i < 4; i++) {
        const int idx = tid + i * 256;
        const int n = idx >> 5, ch = idx & 31;
        cp16(sbase + (uint32_t)(n * KCHUNK + ((ch ^ n) << 4)),
             g_zqT + (size_t)n * Nn + k0 + ch * 16);
    }
    asm volatile("cp.async.commit_group;" ::: "memory");

    // A fragment pointer: row = row0+m0+(lane>>2), byte = 4*(lane&3)
    const unsigned char* aP =
        g_adjq + (size_t)(row0 + m0 + (lane >> 2)) * Nn + k0 + 4 * (lane & 3);

    // B ldmatrix per-lane row indices (x4 covers nt0, nt0+1)
    const int nA = ((lane >> 4) << 3) + (lane & 7);   // 0..15
    const int cb = (lane >> 3) & 1;                   // chunk parity within k32

    asm volatile("cp.async.wait_group 0;" ::: "memory");
    __syncthreads();   // the ONLY barrier

    int c[4][4];
#pragma unroll
    for (int nt = 0; nt < 4; nt++)
#pragma unroll
        for (int j = 0; j < 4; j++) c[nt][j] = 0;

    uint32_t A0[2][4], A1[2][4];
#define LDA(dst, T)                                                              \
    {                                                                            \
        const unsigned char* p = aP + (T) * 64;                                  \
        _Pragma("unroll")                                                        \
        for (int kk = 0; kk < 2; kk++) {                                         \
            dst[kk][0] = __ldg((const unsigned*)(p + kk * 32));                  \
            dst[kk][1] = __ldg((const unsigned*)(p + kk * 32 + (size_t)8 * Nn)); \
            dst[kk][2] = __ldg((const unsigned*)(p + kk * 32 + 16));             \
            dst[kk][3] = __ldg((const unsigned*)(p + kk * 32 + 16 + (size_t)8 * Nn)); \
        }                                                                        \
    }

    LDA(A0, 0)

#pragma unroll
    for (int t = 0; t < NTILE; t++) {
        uint32_t(*Ac)[4] = (t & 1) ? A1 : A0;
        uint32_t(*An)[4] = (t & 1) ? A0 : A1;
        if (t + 1 < NTILE) LDA(An, t + 1)

#pragma unroll
        for (int kk = 0; kk < 2; kk++) {
            const int cL = t * 4 + kk * 2 + cb;  // logical 16B chunk within row
            uint32_t b[4][2];
#pragma unroll
            for (int half = 0; half < 2; half++) {  // nt0 = 0, 2
                const int n = half * 16 + nA;
                const uint32_t addr = sbase + (uint32_t)(n * KCHUNK + ((cL ^ n) << 4));
                asm volatile(
                    "ldmatrix.sync.aligned.m8n8.x4.shared.b16 {%0,%1,%2,%3}, [%4];"
                    : "=r"(b[half * 2][0]), "=r"(b[half * 2][1]),
                      "=r"(b[half * 2 + 1][0]), "=r"(b[half * 2 + 1][1])
                    : "r"(addr));
            }
#pragma unroll
            for (int nt = 0; nt < 4; nt++) {
                asm volatile(
                    "mma.sync.aligned.m16n8k32.row.col.s32.u8.s8.s32 "
                    "{%0,%1,%2,%3}, {%4,%5,%6,%7}, {%8,%9}, {%0,%1,%2,%3};"
                    : "+r"(c[nt][0]), "+r"(c[nt][1]), "+r"(c[nt][2]), "+r"(c[nt][3])
                    : "r"(Ac[kk][0]), "r"(Ac[kk][1]), "r"(Ac[kk][2]), "r"(Ac[kk][3]),
                      "r"(b[nt][0]), "r"(b[nt][1]));
            }
        }
    }
#undef LDA

    // write s32 partials (m16n8 C lane layout)
    int* pp = g_part + (size_t)ks * Nn * HID;
    const int g  = lane >> 2;
    const int tg = lane & 3;
    const int rbase = row0 + m0;
#pragma unroll
    for (int nt = 0; nt < 4; nt++) {
        const int col = nt * 8 + tg * 2;
        *reinterpret_cast<int2*>(&pp[(size_t)(rbase + g) * HID + col]) =
            make_int2(c[nt][0], c[nt][1]);
        *reinterpret_cast<int2*>(&pp[(size_t)(rbase + g + 8) * HID + col]) =
            make_int2(c[nt][2], c[nt][3]);
    }
}

// ---------------------------------------------------------------------------
// Fused: h = relu(dinv⊙(dequant(Σpartials)+zs));  zs' = dinv⊙(h@W2+b2); colmax[1]
// ---------------------------------------------------------------------------
__global__ __launch_bounds__(256) void epi1_z2_kernel(const float* __restrict__ W2,
                                                      const float* __restrict__ b2) {
    __shared__ float hs[32][HID + 1];
    __shared__ float W2s[HID * HID];
    __shared__ unsigned cm[HID];
    int tid = threadIdx.x;
    int r = tid >> 3;
    int c0 = (tid & 7) << 2;
    int row = blockIdx.x * 32 + r;
    int idx4 = (row * HID + c0) >> 2;

    for (int i = tid; i < HID * HID; i += 256) W2s[i] = W2[i];
    if (tid < HID) cm[tid] = 0u;

    int4 S = reinterpret_cast<const int4*>(g_part)[idx4];
#pragma unroll
    for (int p = 1; p < KSPLIT; p++) {
        int4 v = reinterpret_cast<const int4*>(g_part + (size_t)p * Nn * HID)[idx4];
        S.x += v.x; S.y += v.y; S.z += v.z; S.w += v.w;
    }
    float4 zs = reinterpret_cast<const float4*>(g_zs)[idx4];
    float di = g_dinv[row];
    const float inv = 1.0f / 32385.0f;  // 1/(127*255)
    float f0 = __uint_as_float(g_cmbits[0][c0 + 0]) * inv;
    float f1 = __uint_as_float(g_cmbits[0][c0 + 1]) * inv;
    float f2 = __uint_as_float(g_cmbits[0][c0 + 2]) * inv;
    float f3 = __uint_as_float(g_cmbits[0][c0 + 3]) * inv;
    hs[r][c0 + 0] = fmaxf(di * (S.x * f0 + zs.x), 0.f);
    hs[r][c0 + 1] = fmaxf(di * (S.y * f1 + zs.y), 0.f);
    hs[r][c0 + 2] = fmaxf(di * (S.z * f2 + zs.z), 0.f);
    hs[r][c0 + 3] = fmaxf(di * (S.w * f3 + zs.w), 0.f);
    __syncthreads();

    float acc[4] = { b2[c0], b2[c0 + 1], b2[c0 + 2], b2[c0 + 3] };
#pragma unroll
    for (int k = 0; k < HID; k++) {
        float hv = hs[r][k];
        acc[0] += hv * W2s[k * HID + c0 + 0];
        acc[1] += hv * W2s[k * HID + c0 + 1];
        acc[2] += hv * W2s[k * HID + c0 + 2];
        acc[3] += hv * W2s[k * HID + c0 + 3];
    }
    float4 o;
    o.x = di * acc[0]; o.y = di * acc[1]; o.z = di * acc[2]; o.w = di * acc[3];
    reinterpret_cast<float4*>(g_zs)[idx4] = o;
    atomicMax(&cm[c0 + 0], __float_as_uint(fabsf(o.x)));
    atomicMax(&cm[c0 + 1], __float_as_uint(fabsf(o.y)));
    atomicMax(&cm[c0 + 2], __float_as_uint(fabsf(o.z)));
    atomicMax(&cm[c0 + 3], __float_as_uint(fabsf(o.w)));
    __syncthreads();
    if (tid < HID) atomicMax(&g_cmbits[1][tid], cm[tid]);
}

// ---------------------------------------------------------------------------
// Epilogue L2 + final: logits = relu(dinv⊙(dequant+zs)) @ W3 + b3
// ---------------------------------------------------------------------------
__global__ __launch_bounds__(256) void epilogue_final_kernel(const float* __restrict__ W3,
                                                             const float* __restrict__ b3,
                                                             float* __restrict__ out) {
    int tid = threadIdx.x;
    int idx4 = blockIdx.x * 256 + tid;
    int row = idx4 >> 3;
    int c0 = (idx4 & 7) << 2;
    int4 S = reinterpret_cast<const int4*>(g_part)[idx4];
#pragma unroll
    for (int p = 1; p < KSPLIT; p++) {
        int4 v = reinterpret_cast<const int4*>(g_part + (size_t)p * Nn * HID)[idx4];
        S.x += v.x; S.y += v.y; S.z += v.z; S.w += v.w;
    }
    float4 zs = reinterpret_cast<const float4*>(g_zs)[idx4];
    float di = g_dinv[row];
    const float inv = 1.0f / 32385.0f;
    float f0 = __uint_as_float(g_cmbits[1][c0 + 0]) * inv;
    float f1 = __uint_as_float(g_cmbits[1][c0 + 1]) * inv;
    float f2 = __uint_as_float(g_cmbits[1][c0 + 2]) * inv;
    float f3 = __uint_as_float(g_cmbits[1][c0 + 3]) * inv;
    float h0 = fmaxf(di * (S.x * f0 + zs.x), 0.f);
    float h1 = fmaxf(di * (S.y * f1 + zs.y), 0.f);
    float h2 = fmaxf(di * (S.z * f2 + zs.z), 0.f);
    float h3 = fmaxf(di * (S.w * f3 + zs.w), 0.f);
    float v = h0 * W3[c0] + h1 * W3[c0 + 1] + h2 * W3[c0 + 2] + h3 * W3[c0 + 3];
#pragma unroll
    for (int o = 4; o; o >>= 1) v += __shfl_xor_sync(0xffffffffu, v, o);
    if ((tid & 7) == 0) out[row] = v + b3[0];
}

// ---------------------------------------------------------------------------
extern "C" void kernel_launch(void* const* d_in, const int* in_sizes, int n_in,
                              void* d_out, int out_size) {
    const float* x   = (const float*)d_in[0];
    const float* adj = (const float*)d_in[1];
    const float* W1  = (const float*)d_in[2];
    const float* b1  = (const float*)d_in[3];
    const float* W2  = (const float*)d_in[4];
    const float* b2  = (const float*)d_in[5];
    const float* W3  = (const float*)d_in[6];
    const float* b3  = (const float*)d_in[7];
    float* out = (float*)d_out;

    degree_convert_kernel<<<Nn, 256>>>(adj);
    z1_kernel<<<Nn / 8, 256>>>(x, W1, b1);
    quantT_kernel<<<Nn / 128, 256>>>(0);
    spmm_mma_kernel<<<(Nn / BM) * KSPLIT, 256>>>();   // layer 1 partials (s32)
    epi1_z2_kernel<<<Nn / 32, 256>>>(W2, b2);         // h + z2 fused -> g_zs
    quantT_kernel<<<Nn / 128, 256>>>(1);
    spmm_mma_kernel<<<(Nn / BM) * KSPLIT, 256>>>();   // layer 2 partials (s32)
    epilogue_final_kernel<<<Nn * HID / 4 / 256, 256>>>(W3, b3, out);
}